// round 15
// baseline (speedup 1.0000x reference)
#include <cuda_runtime.h>
#include <cuda_fp16.h>
#include <cstdint>

// ---------------------------------------------------------------------------
// Actor_22625887715353 — round 15: round-13 GEMM core (best: 128x128x64,
// 2 CTAs/SM, static strided schedule, softmax fused in G3) + PREP PULLED INTO
// the persistent kernel as fine-grained flagged work items so the ~11us of
// HBM-bound conversion overlaps the GEMM ramp instead of serializing.
// Items: 128 x-cast quarters + 64 w1^T quarters + 32 w2^T quarters +
// 10 head-pack strips (incl bias) -> then 512 G1 + 256 G2 + 320 G3 tiles.
// G1 gates on xc/w1t flags, G2 on cnt1+w2t, G3 on cnt2+wp. g_sync[] zeroed
// by a captured cudaMemsetAsync.
// ---------------------------------------------------------------------------

constexpr int BSZ = 4096, IN_DIM = 2048, HID = 2048, H2 = 1024, NHC = 1280;

// ---- device scratch (no cudaMalloc allowed) ----
__device__ __half g_xh[BSZ * IN_DIM];
__device__ __half g_w1h[HID * IN_DIM];     // [N=2048, K=2048]
__device__ __half g_w2h[H2 * HID];         // [N=1024, K=2048]
__device__ __half g_wph[NHC * H2];         // [N=1280, K=1024]
__device__ __half g_h1h[BSZ * HID];
__device__ __half g_h2h[BSZ * H2];
__device__ float g_bpack[NHC];

// sync flags: xc[32](==4) | w1t[16](==4) | w2t[8](==4) | wp[10](==1)
//             | cnt1[32](==16) | cnt2[32](==8)
constexpr int S_XC = 0, S_W1 = 32, S_W2 = 48, S_WP = 56, S_C1 = 66, S_C2 = 98;
constexpr int NSYNC = 130;
__device__ int g_sync[NSYNC];

// ===========================================================================
// Low-level helpers (family-agnostic sm_80+ ISA)
// ===========================================================================
__device__ __forceinline__ uint32_t cvta_s(const void* p) {
    uint32_t a;
    asm("{ .reg .u64 t; cvta.to.shared.u64 t, %1; cvt.u32.u64 %0, t; }" : "=r"(a) : "l"(p));
    return a;
}
__device__ __forceinline__ int ld_acq(const int* p) {
    int v;
    asm volatile("ld.acquire.gpu.global.b32 %0, [%1];" : "=r"(v) : "l"(p) : "memory");
    return v;
}
#define CP16(d, s) asm volatile("cp.async.cg.shared.global [%0], [%1], 16;" :: "r"(d), "l"(s))
#define CP_COMMIT  asm volatile("cp.async.commit_group;")
#define CP_WAIT1   asm volatile("cp.async.wait_group 1;")
#define LDSM4(r0, r1, r2, r3, a) \
    asm volatile("ldmatrix.sync.aligned.m8n8.x4.shared.b16 {%0,%1,%2,%3}, [%4];" \
                 : "=r"(r0), "=r"(r1), "=r"(r2), "=r"(r3) : "r"(a))
#define MMA_F16(d, a, b) \
    asm volatile("mma.sync.aligned.m16n8k16.row.col.f32.f16.f16.f32 " \
                 "{%0,%1,%2,%3},{%4,%5,%6,%7},{%8,%9},{%0,%1,%2,%3};" \
                 : "+f"((d)[0]), "+f"((d)[1]), "+f"((d)[2]), "+f"((d)[3]) \
                 : "r"((a)[0]), "r"((a)[1]), "r"((a)[2]), "r"((a)[3]), \
                   "r"((b)[0]), "r"((b)[1]))

// ===========================================================================
// Tile geometry (rounds 7-13): CTA 128x128x64, 3-stage cp.async, 96 KB smem.
// ===========================================================================
constexpr int BM = 128, BN = 128, BK = 64, STAGES = 3;
constexpr int TB1 = BM * 64;
constexpr int SM_A0 = 0, SM_A1 = TB1, SM_B0 = 2 * TB1, SM_B1 = 3 * TB1;
constexpr int STB = 4 * TB1;                   // 32 KB per stage
constexpr int GEMM_SMEM = STAGES * STB;        // 96 KB

constexpr int NWORK   = 296;                   // 148 SMs x 2 CTAs (all resident)
constexpr int NPREP   = 234;                   // 128 xc + 64 w1t + 32 w2t + 10 wp
constexpr int NT_G1   = 512;                   // 32 strips x 16
constexpr int NT_G2   = 256;                   // 32 strips x 8
constexpr int NT_G3   = 320;                   // 32 strips x 10
constexpr int N_ITEMS = NPREP + NT_G1 + NT_G2 + NT_G3;   // 1322

// ===========================================================================
// Prep items (coalesced, smem 32x33 tile transposes; round-9 logic split
// into strip-granular flagged items). Each ends: fence + sync + flag bump.
// ===========================================================================
__device__ __forceinline__ void prep_item(
    char* smem, int item,
    const float* __restrict__ x,  const float* __restrict__ w1,
    const float* __restrict__ w2, const float* __restrict__ wr,
    const float* __restrict__ br, const float* __restrict__ wl,
    const float* __restrict__ bl)
{
    float (*t)[33] = (float(*)[33])smem;
    const int tid = threadIdx.x, tx = tid & 31, ty = tid >> 5;
    int flag;

    if (item < 128) {                          // ---- x cast quarter-strip ----
        const int s = item >> 2, q = item & 3;
        const int r0 = s * 128 + q * 32;       // 32 rows x 2048 cols
        const float* src = x + (size_t)r0 * IN_DIM;
        __half* dst = g_xh + (size_t)r0 * IN_DIM;
        for (int j = tid * 4; j < 32 * IN_DIM; j += 1024) {
            float4 v = *(const float4*)(src + j);
            __half2 a, b;
            a.x = __float2half_rn(v.x); a.y = __float2half_rn(v.y);
            b.x = __float2half_rn(v.z); b.y = __float2half_rn(v.w);
            *(__half2*)(dst + j) = a;
            *(__half2*)(dst + j + 2) = b;
        }
        flag = S_XC + s;
    } else if (item < 192) {                   // ---- w1^T quarter-strip ----
        const int i = item - 128, n = i >> 2, kq = i & 3;
        const int k0 = kq * 512, n0 = n * 128;
        for (int tt = 0; tt < 64; tt++) {      // 16 k-tiles x 4 col-tiles
            const int r0 = k0 + (tt >> 2) * 32, c0 = n0 + (tt & 3) * 32;
#pragma unroll
            for (int k = 0; k < 4; k++)
                t[ty + 8 * k][tx] = w1[(size_t)(r0 + ty + 8 * k) * HID + c0 + tx];
            __syncthreads();
#pragma unroll
            for (int k = 0; k < 4; k++)
                g_w1h[(size_t)(c0 + ty + 8 * k) * IN_DIM + r0 + tx] =
                    __float2half_rn(t[tx][ty + 8 * k]);
            __syncthreads();
        }
        flag = S_W1 + n;
    } else if (item < 224) {                   // ---- w2^T quarter-strip ----
        const int i = item - 192, n = i >> 2, kq = i & 3;
        const int k0 = kq * 512, n0 = n * 128;
        for (int tt = 0; tt < 64; tt++) {
            const int r0 = k0 + (tt >> 2) * 32, c0 = n0 + (tt & 3) * 32;
#pragma unroll
            for (int k = 0; k < 4; k++)
                t[ty + 8 * k][tx] = w2[(size_t)(r0 + ty + 8 * k) * H2 + c0 + tx];
            __syncthreads();
#pragma unroll
            for (int k = 0; k < 4; k++)
                g_w2h[(size_t)(c0 + ty + 8 * k) * HID + r0 + tx] =
                    __float2half_rn(t[tx][ty + 8 * k]);
            __syncthreads();
        }
        flag = S_W2 + n;
    } else {                                   // ---- head-pack strip + bias ----
        const int n = item - 224;
        if (n < 8) {                           // RSU rows [n*128, +128)
            for (int kh = n * 4; kh < n * 4 + 4; kh++) {
                const float* wrk = wr + (size_t)kh * H2 * 32;
                for (int h0 = 0; h0 < H2; h0 += 32) {
#pragma unroll
                    for (int k = 0; k < 4; k++)
                        t[ty + 8 * k][tx] = wrk[(size_t)(h0 + ty + 8 * k) * 32 + tx];
                    __syncthreads();
#pragma unroll
                    for (int k = 0; k < 4; k++)
                        g_wph[(size_t)(kh * 32 + ty + 8 * k) * H2 + h0 + tx] =
                            __float2half_rn(t[tx][ty + 8 * k]);
                    __syncthreads();
                }
            }
            if (tid < 128) g_bpack[n * 128 + tid] = br[n * 128 + tid];
        } else {                               // LAY rows 1024+[(n-8)*128, +128)
            const int n2 = n - 8;
            for (int kh = n2 * 16; kh < n2 * 16 + 16; kh++) {
                for (int h0 = 0; h0 < H2; h0 += 32) {
                    t[tid >> 3][tid & 7] = wl[(size_t)kh * H2 * 8 + h0 * 8 + tid];
                    __syncthreads();
                    g_wph[(size_t)(1024 + kh * 8 + ty) * H2 + h0 + tx] =
                        __float2half_rn(t[tx][ty]);
                    __syncthreads();
                }
            }
            if (tid < 128) g_bpack[1024 + n2 * 128 + tid] = bl[n2 * 128 + tid];
        }
        flag = S_WP + n;
    }
    __threadfence();
    __syncthreads();
    if (tid == 0) atomicAdd(&g_sync[flag], 1);
}

// ===========================================================================
// Specialized tile worker (round 13, unchanged): constexpr K per GEMM.
// ===========================================================================
template <int K, bool SMAX>
__device__ __forceinline__ void run_tile(
    uint32_t sb, const __half* __restrict__ A, const __half* __restrict__ B,
    const float* __restrict__ bias, __half* __restrict__ oh,
    float* __restrict__ of, int No, int bm, int bn)
{
    const int tid = threadIdx.x, lane = tid & 31, warp = tid >> 5;
    const int m0w = (warp >> 2) * 64, n0w = (warp & 3) * 32;
    const int lr = tid >> 2, lc = tid & 3;

    const int rA = lane & 15;
    const int hA = lane >> 4;
    const int rB = (lane & 7) + ((lane >> 4) << 3);
    const int hB = (lane >> 3) & 1;

    auto load_stage = [&](int s, int kc) {
        const uint32_t stb = sb + s * STB;
#pragma unroll
        for (int sub = 0; sub < 2; sub++) {
            const int kg = kc * BK + sub * 32 + lc * 8;
            const uint32_t sa = stb + (sub ? SM_A1 : SM_A0);
            const uint32_t sbb = stb + (sub ? SM_B1 : SM_B0);
#pragma unroll
            for (int h = 0; h < 2; h++) {
                const int r = lr + h * 64;
                const uint32_t sw = r * 64 + ((lc ^ ((r >> 1) & 3)) << 4);
                CP16(sa + sw,  A + (size_t)(bm + r) * K + kg);
                CP16(sbb + sw, B + (size_t)(bn + r) * K + kg);
            }
        }
    };

    float acc[4][4][4];
#pragma unroll
    for (int a = 0; a < 4; a++)
#pragma unroll
        for (int b = 0; b < 4; b++)
#pragma unroll
            for (int c = 0; c < 4; c++) acc[a][b][c] = 0.f;

    constexpr int NS = K / BK;
    load_stage(0, 0); CP_COMMIT;
    load_stage(1, 1); CP_COMMIT;

    int s_cur = 0, s_load = 2;
    for (int i = 0; i < NS; i++) {
        CP_WAIT1;
        __syncthreads();
        if (i + 2 < NS) load_stage(s_load, i + 2);
        CP_COMMIT;
        if (++s_load == STAGES) s_load = 0;

        const uint32_t stb = sb + s_cur * STB;
        if (++s_cur == STAGES) s_cur = 0;
#pragma unroll
        for (int sub = 0; sub < 2; sub++) {
            const uint32_t sa = stb + (sub ? SM_A1 : SM_A0);
            const uint32_t sbb = stb + (sub ? SM_B1 : SM_B0);
#pragma unroll
            for (int ks = 0; ks < 2; ks++) {
                uint32_t ahf[4][4], bf[4][2];
#pragma unroll
                for (int mf = 0; mf < 4; mf++) {
                    const int r = m0w + mf * 16 + rA;
                    const uint32_t off = r * 64 + (((ks * 2 + hA) ^ ((r >> 1) & 3)) << 4);
                    LDSM4(ahf[mf][0], ahf[mf][1], ahf[mf][2], ahf[mf][3], sa + off);
                }
#pragma unroll
                for (int p = 0; p < 2; p++) {
                    const int r = n0w + p * 16 + rB;
                    const uint32_t off = r * 64 + (((ks * 2 + hB) ^ ((r >> 1) & 3)) << 4);
                    uint32_t q0, q1, q2, q3;
                    LDSM4(q0, q1, q2, q3, sbb + off);
                    bf[2 * p][0] = q0; bf[2 * p][1] = q1;
                    bf[2 * p + 1][0] = q2; bf[2 * p + 1][1] = q3;
                }
#pragma unroll
                for (int mf = 0; mf < 4; mf++)
#pragma unroll
                    for (int nf = 0; nf < 4; nf++) MMA_F16(acc[mf][nf], ahf[mf], bf[nf]);
            }
        }
    }

    if (!SMAX) {
#pragma unroll
        for (int mf = 0; mf < 4; mf++)
#pragma unroll
            for (int nf = 0; nf < 4; nf++) {
                const int col = bn + n0w + nf * 8 + (lane & 3) * 2;
                const float bx = __ldg(bias + col), by = __ldg(bias + col + 1);
#pragma unroll
                for (int h = 0; h < 2; h++) {
                    const int row = bm + m0w + mf * 16 + (lane >> 2) + h * 8;
                    float v0 = fmaxf(acc[mf][nf][2 * h]     + bx, 0.f);
                    float v1 = fmaxf(acc[mf][nf][2 * h + 1] + by, 0.f);
                    __half2 p;
                    p.x = __float2half_rn(v0); p.y = __float2half_rn(v1);
                    *(__half2*)(oh + (size_t)row * No + col) = p;
                }
            }
    } else {
        const int nbase = bn + n0w;            // warp-uniform
#pragma unroll
        for (int mf = 0; mf < 4; mf++)
#pragma unroll
            for (int h = 0; h < 2; h++) {
                const int row = bm + m0w + mf * 16 + (lane >> 2) + h * 8;
                float* orow = of + (size_t)row * NHC;
                float v[8];
#pragma unroll
                for (int nf = 0; nf < 4; nf++) {
                    const int col = nbase + nf * 8 + (lane & 3) * 2;
                    v[2 * nf]     = acc[mf][nf][2 * h]     + __ldg(bias + col);
                    v[2 * nf + 1] = acc[mf][nf][2 * h + 1] + __ldg(bias + col + 1);
                }
                if (nbase < 1024) {            // RSU head (width 32)
                    float m = v[0];
#pragma unroll
                    for (int j = 1; j < 8; j++) m = fmaxf(m, v[j]);
                    m = fmaxf(m, __shfl_xor_sync(0xffffffffu, m, 1));
                    m = fmaxf(m, __shfl_xor_sync(0xffffffffu, m, 2));
                    float s = 0.f;
#pragma unroll
                    for (int j = 0; j < 8; j++) { v[j] = __expf(v[j] - m); s += v[j]; }
                    s += __shfl_xor_sync(0xffffffffu, s, 1);
                    s += __shfl_xor_sync(0xffffffffu, s, 2);
                    const float inv = 1.f / s;
                    const int k = nbase >> 5;
                    const int ob = (k >> 1) * 80 + (k & 1) * 32 + (lane & 3) * 2;
#pragma unroll
                    for (int nf = 0; nf < 4; nf++)
                        *(float2*)(orow + ob + nf * 8) =
                            make_float2(v[2 * nf] * inv, v[2 * nf + 1] * inv);
                } else {                       // LAY heads (width 8)
#pragma unroll
                    for (int nf = 0; nf < 4; nf++) {
                        float a0 = v[2 * nf], a1 = v[2 * nf + 1];
                        float m = fmaxf(a0, a1);
                        m = fmaxf(m, __shfl_xor_sync(0xffffffffu, m, 1));
                        m = fmaxf(m, __shfl_xor_sync(0xffffffffu, m, 2));
                        const float e0 = __expf(a0 - m), e1 = __expf(a1 - m);
                        float s = e0 + e1;
                        s += __shfl_xor_sync(0xffffffffu, s, 1);
                        s += __shfl_xor_sync(0xffffffffu, s, 2);
                        const float inv = 1.f / s;
                        const int k = (nbase + nf * 8 - 1024) >> 3;
                        const int ob = (k >> 1) * 80 + 64 + (k & 1) * 8 + (lane & 3) * 2;
                        *(float2*)(orow + ob) = make_float2(e0 * inv, e1 * inv);
                    }
                }
            }
    }
}

// ===========================================================================
// Persistent fused kernel: prep items then G1/G2/G3, static strided schedule.
// Prep items never block; G1 waits xc+w1t flags; G2 waits cnt1+w2t; G3 waits
// cnt2+wp. All 296 workers resident -> acyclic, deadlock-free.
// ===========================================================================
__global__ __launch_bounds__(256, 2) void fused_all(
    const float* __restrict__ x,  const float* __restrict__ w1,
    const float* __restrict__ b1, const float* __restrict__ w2,
    const float* __restrict__ b2, const float* __restrict__ wr,
    const float* __restrict__ br, const float* __restrict__ wl,
    const float* __restrict__ bl, float* __restrict__ out)
{
    extern __shared__ char smem[];
    const uint32_t sb = cvta_s(smem);
    const int tid = threadIdx.x;

    for (int item = blockIdx.x; item < N_ITEMS; item += NWORK) {
        if (item < NPREP) {
            __syncthreads();   // smem reuse guard
            prep_item(smem, item, x, w1, w2, wr, br, wl, bl);
        } else if (item < NPREP + NT_G1) {
            const int it = item - NPREP;
            const int bm = (it >> 4) * BM, bn = (it & 15) * BN;
            if (tid == 0) {
                while (ld_acq(&g_sync[S_XC + (bm >> 7)]) < 4) __nanosleep(64);
                while (ld_acq(&g_sync[S_W1 + (bn >> 7)]) < 4) __nanosleep(64);
            }
            __syncthreads();
            run_tile<IN_DIM, false>(sb, g_xh, g_w1h, b1, g_h1h, nullptr, HID, bm, bn);
            __threadfence();
            __syncthreads();
            if (tid == 0) atomicAdd(&g_sync[S_C1 + (bm >> 7)], 1);
        } else if (item < NPREP + NT_G1 + NT_G2) {
            const int i = item - NPREP - NT_G1;
            const int bm = (i >> 3) * BM, bn = (i & 7) * BN;
            if (tid == 0) {
                while (ld_acq(&g_sync[S_C1 + (bm >> 7)]) < 16) __nanosleep(64);
                while (ld_acq(&g_sync[S_W2 + (bn >> 7)]) < 4) __nanosleep(64);
            }
            __syncthreads();
            run_tile<HID, false>(sb, g_h1h, g_w2h, b2, g_h2h, nullptr, H2, bm, bn);
            __threadfence();
            __syncthreads();
            if (tid == 0) atomicAdd(&g_sync[S_C2 + (bm >> 7)], 1);
        } else {
            const int i = item - NPREP - NT_G1 - NT_G2;
            const int bm = (i / 10) * BM, bn = (i % 10) * BN;
            if (tid == 0) {
                while (ld_acq(&g_sync[S_C2 + (bm >> 7)]) < 8) __nanosleep(64);
                while (ld_acq(&g_sync[S_WP + (bn >> 7)]) < 1) __nanosleep(64);
            }
            __syncthreads();
            run_tile<H2, true>(sb, g_h2h, g_wph, g_bpack, nullptr, out, NHC, bm, bn);
            __syncthreads();   // protect smem before next item
        }
    }
}

// ===========================================================================
// Host side
// ===========================================================================
extern "C" void kernel_launch(void* const* d_in, const int* in_sizes, int n_in,
                              void* d_out, int out_size)
{
    const float* x  = (const float*)d_in[0];
    const float* w1 = (const float*)d_in[1];
    const float* b1 = (const float*)d_in[2];
    const float* w2 = (const float*)d_in[3];
    const float* b2 = (const float*)d_in[4];
    const float* wr = (const float*)d_in[5];
    const float* br = (const float*)d_in[6];
    const float* wl = (const float*)d_in[7];
    const float* bl = (const float*)d_in[8];
    float* out = (float*)d_out;

    void* syncp;
    cudaGetSymbolAddress(&syncp, g_sync);

    cudaFuncSetAttribute(fused_all,
                         cudaFuncAttributeMaxDynamicSharedMemorySize, GEMM_SMEM);

    // zero flags (captured graph node; no allocation)
    cudaMemsetAsync(syncp, 0, NSYNC * sizeof(int));

    // ONE persistent kernel: prep + GEMM1 + GEMM2 + GEMM3(+softmax)
    fused_all<<<NWORK, 256, GEMM_SMEM>>>(x, w1, b1, w2, b2, wr, br, wl, bl, out);
}